// round 1
// baseline (speedup 1.0000x reference)
#include <cuda_runtime.h>
#include <cuda_bf16.h>

#define NN 5200    // nodes
#define NI 5200    // incidences
#define NH 1000    // hyperedges
#define ND 4096    // feature dim
#define NEG 0.01f

// ---------------- device scratch (no allocations allowed) ----------------
__device__ float g_D[NN];
__device__ float g_B[NH];
__device__ float g_Dinv[NN];
__device__ float g_Binv[NH];
__device__ int   g_ncnt[NN];
__device__ int   g_ecnt[NH];
__device__ int   g_noff[NN + 1];
__device__ int   g_eoff[NH + 1];
__device__ int   g_ncur[NN];
__device__ int   g_ecur[NH];
__device__ int   g_ncsr[NI];   // per-node list of edge ids
__device__ int   g_ecsr[NI];   // per-edge list of node ids
__device__ float g_eout[(size_t)NH * ND];  // raw edge_out (pre-leaky) scratch

// ---------------- K0: zero counters/accumulators ----------------
__global__ void k_zero() {
    int i = blockIdx.x * blockDim.x + threadIdx.x;
    if (i < NN) { g_D[i] = 0.f; g_ncnt[i] = 0; }
    if (i < NH) { g_B[i] = 0.f; g_ecnt[i] = 0; }
}

// ---------------- K1: degree sums + CSR counts ----------------
__global__ void k_count(const int* __restrict__ node_idx,
                        const int* __restrict__ edge_idx,
                        const float* __restrict__ hw,
                        const float* __restrict__ norm) {
    int i = blockIdx.x * blockDim.x + threadIdx.x;
    if (i >= NI) return;
    int n = node_idx[i];
    int e = edge_idx[i];
    atomicAdd(&g_D[n], hw[e]);
    atomicAdd(&g_B[e], norm[n]);
    atomicAdd(&g_ncnt[n], 1);
    atomicAdd(&g_ecnt[e], 1);
}

// ---------------- block-wide inclusive scan helper ----------------
__device__ __forceinline__ int blk_scan_incl(int v, int* ws) {
    int lane = threadIdx.x & 31;
    int w    = threadIdx.x >> 5;
#pragma unroll
    for (int o = 1; o < 32; o <<= 1) {
        int t = __shfl_up_sync(0xffffffffu, v, o);
        if (lane >= o) v += t;
    }
    if (lane == 31) ws[w] = v;
    __syncthreads();
    if (w == 0) {
        int nw = blockDim.x >> 5;
        int s = (lane < nw) ? ws[lane] : 0;
#pragma unroll
        for (int o = 1; o < 32; o <<= 1) {
            int t = __shfl_up_sync(0xffffffffu, s, o);
            if (lane >= o) s += t;
        }
        ws[lane] = s;
    }
    __syncthreads();
    if (w > 0) v += ws[w - 1];
    return v;
}

// ---------------- K2: prefix sums -> offsets, cursors, inverses ----------------
__global__ void k_scan() {
    __shared__ int ws[32];
    int nw = blockDim.x >> 5;

    // edge offsets
    int carry = 0;
    for (int base = 0; base < NH; base += blockDim.x) {
        __syncthreads();
        int i = base + threadIdx.x;
        int v = (i < NH) ? g_ecnt[i] : 0;
        int s = blk_scan_incl(v, ws);
        if (i < NH) g_eoff[i + 1] = carry + s;
        __syncthreads();
        carry += ws[nw - 1];
    }
    if (threadIdx.x == 0) g_eoff[0] = 0;

    // node offsets
    carry = 0;
    for (int base = 0; base < NN; base += blockDim.x) {
        __syncthreads();
        int i = base + threadIdx.x;
        int v = (i < NN) ? g_ncnt[i] : 0;
        int s = blk_scan_incl(v, ws);
        if (i < NN) g_noff[i + 1] = carry + s;
        __syncthreads();
        carry += ws[nw - 1];
    }
    if (threadIdx.x == 0) g_noff[0] = 0;
    __syncthreads();

    // cursors + reciprocals
    for (int i = threadIdx.x; i < NH; i += blockDim.x) {
        g_ecur[i] = g_eoff[i];
        float b = g_B[i];
        g_Binv[i] = (b == 0.f) ? 0.f : 1.f / b;
    }
    for (int i = threadIdx.x; i < NN; i += blockDim.x) {
        g_ncur[i] = g_noff[i];
        float d = g_D[i];
        g_Dinv[i] = (d == 0.f) ? 0.f : 1.f / d;
    }
}

// ---------------- K3: scatter incidences into CSR lists ----------------
__global__ void k_scatter(const int* __restrict__ node_idx,
                          const int* __restrict__ edge_idx) {
    int i = blockIdx.x * blockDim.x + threadIdx.x;
    if (i >= NI) return;
    int n = node_idx[i];
    int e = edge_idx[i];
    int p = atomicAdd(&g_ecur[e], 1);
    g_ecsr[p] = n;
    int q = atomicAdd(&g_ncur[n], 1);
    g_ncsr[q] = e;
}

// ---------------- K4: edge aggregation (phase 1) ----------------
// grid: (NH, ND/1024), block: 256 threads, float4 per thread
__global__ void __launch_bounds__(256) k_edge(const float* __restrict__ feat,
                                              float* __restrict__ out_edge) {
    int e  = blockIdx.x;
    int d0 = blockIdx.y * 1024 + threadIdx.x * 4;
    int s = g_eoff[e];
    int t = g_eoff[e + 1];
    float4 acc = make_float4(0.f, 0.f, 0.f, 0.f);
    for (int j = s; j < t; j++) {
        int n = g_ecsr[j];
        float4 v = *reinterpret_cast<const float4*>(feat + (size_t)n * ND + d0);
        acc.x += v.x; acc.y += v.y; acc.z += v.z; acc.w += v.w;
    }
    float b = g_Binv[e];
    acc.x *= b; acc.y *= b; acc.z *= b; acc.w *= b;
    // raw edge_out for phase 2
    *reinterpret_cast<float4*>(g_eout + (size_t)e * ND + d0) = acc;
    // leaky-relu edge output
    float4 lr;
    lr.x = acc.x > 0.f ? acc.x : NEG * acc.x;
    lr.y = acc.y > 0.f ? acc.y : NEG * acc.y;
    lr.z = acc.z > 0.f ? acc.z : NEG * acc.z;
    lr.w = acc.w > 0.f ? acc.w : NEG * acc.w;
    *reinterpret_cast<float4*>(out_edge + (size_t)e * ND + d0) = lr;
}

// ---------------- K5: node aggregation (phase 2) ----------------
// grid: (NN, ND/1024), block: 256 threads, float4 per thread
__global__ void __launch_bounds__(256) k_node(const float* __restrict__ bias,
                                              float* __restrict__ out_node) {
    int n  = blockIdx.x;
    int d0 = blockIdx.y * 1024 + threadIdx.x * 4;
    int s = g_noff[n];
    int t = g_noff[n + 1];
    float4 acc = make_float4(0.f, 0.f, 0.f, 0.f);
    for (int j = s; j < t; j++) {
        int e = g_ncsr[j];
        float4 v = *reinterpret_cast<const float4*>(g_eout + (size_t)e * ND + d0);
        acc.x += v.x; acc.y += v.y; acc.z += v.z; acc.w += v.w;
    }
    float dv = g_Dinv[n];
    float4 bb = *reinterpret_cast<const float4*>(bias + d0);
    acc.x = acc.x * dv + bb.x;
    acc.y = acc.y * dv + bb.y;
    acc.z = acc.z * dv + bb.z;
    acc.w = acc.w * dv + bb.w;
    float4 lr;
    lr.x = acc.x > 0.f ? acc.x : NEG * acc.x;
    lr.y = acc.y > 0.f ? acc.y : NEG * acc.y;
    lr.z = acc.z > 0.f ? acc.z : NEG * acc.z;
    lr.w = acc.w > 0.f ? acc.w : NEG * acc.w;
    *reinterpret_cast<float4*>(out_node + (size_t)n * ND + d0) = lr;
}

// ---------------- launch ----------------
extern "C" void kernel_launch(void* const* d_in, const int* in_sizes, int n_in,
                              void* d_out, int out_size) {
    const float* feat = (const float*)d_in[0];   // features [5200,4096]
    const int*   hidx = (const int*)d_in[1];     // hyperedge_index [2,5200]
    // d_in[2] = hyperedge_type (unused by the computed outputs)
    const float* hw   = (const float*)d_in[3];   // hyperedge_weight [1000]
    // d_in[4], d_in[5] = hyperedge_attr1/2 (unused)
    const float* ew   = (const float*)d_in[6];   // EW_weight [5200]
    const float* bias = (const float*)d_in[7];   // bias [4096]

    const int* node_idx = hidx;        // row 0
    const int* edge_idx = hidx + NI;   // row 1

    float* out      = (float*)d_out;
    float* out_node = out;                       // [5200,4096]
    float* out_edge = out + (size_t)NN * ND;     // [1000,4096]

    k_zero<<<(NN + 255) / 256, 256>>>();
    k_count<<<(NI + 255) / 256, 256>>>(node_idx, edge_idx, hw, ew);
    k_scan<<<1, 1024>>>();
    k_scatter<<<(NI + 255) / 256, 256>>>(node_idx, edge_idx);
    k_edge<<<dim3(NH, ND / 1024), 256>>>(feat, out_edge);
    k_node<<<dim3(NN, ND / 1024), 256>>>(bias, out_node);
}